// round 15
// baseline (speedup 1.0000x reference)
#include <cuda_runtime.h>
#include <cuda_bf16.h>
#include <math.h>
#include <stdint.h>

#define HIDDEN 1024
#define SEQ    2048
#define BATCH  2
#define HEADS  16
#define HD     64
#define MROWS  (BATCH * SEQ)   /* 4096 */

// ---------------------------------------------------------------------------
// Scratch (device globals — no allocation allowed)
// ---------------------------------------------------------------------------
__device__ __align__(16) __nv_bfloat16 g_xhi[(size_t)MROWS * HIDDEN];
__device__ __align__(16) __nv_bfloat16 g_xlo[(size_t)MROWS * HIDDEN];
__device__ __align__(16) __nv_bfloat16 g_qkvhi[(size_t)MROWS * 3 * HIDDEN]; // [4096][3072]
__device__ __align__(16) __nv_bfloat16 g_qkvlo[(size_t)MROWS * 3 * HIDDEN];
__device__ __align__(16) __nv_bfloat16 g_chi[(size_t)MROWS * HIDDEN];
__device__ __align__(16) __nv_bfloat16 g_clo[(size_t)MROWS * HIDDEN];
__device__ __align__(16) __nv_bfloat16 g_wqhi[(size_t)3 * HIDDEN * HIDDEN]; // [3072][1024] K-major
__device__ __align__(16) __nv_bfloat16 g_wqlo[(size_t)3 * HIDDEN * HIDDEN];
__device__ __align__(16) __nv_bfloat16 g_wohi[(size_t)HIDDEN * HIDDEN];     // [1024][1024] K-major
__device__ __align__(16) __nv_bfloat16 g_wolo[(size_t)HIDDEN * HIDDEN];

// ---------------------------------------------------------------------------
// helpers
// ---------------------------------------------------------------------------
__device__ __forceinline__ void mma_bf16(float c[4],
                                         uint32_t a0, uint32_t a1, uint32_t a2, uint32_t a3,
                                         uint32_t b0, uint32_t b1) {
    asm volatile(
        "mma.sync.aligned.m16n8k16.row.col.f32.bf16.bf16.f32 "
        "{%0,%1,%2,%3}, {%4,%5,%6,%7}, {%8,%9}, {%0,%1,%2,%3};"
        : "+f"(c[0]), "+f"(c[1]), "+f"(c[2]), "+f"(c[3])
        : "r"(a0), "r"(a1), "r"(a2), "r"(a3), "r"(b0), "r"(b1));
}
__device__ __forceinline__ uint32_t pack_bf16(float x, float y) {
    __nv_bfloat162 t = __floats2bfloat162_rn(x, y);
    return *(uint32_t*)&t;
}
__device__ __forceinline__ uint32_t lds32(const __nv_bfloat16* p) {
    return *(const uint32_t*)p;
}
__device__ __forceinline__ uint32_t smem_u32(const void* p) {
    uint32_t a;
    asm("{ .reg .u64 t; cvta.to.shared.u64 t, %1; cvt.u32.u64 %0, t; }" : "=r"(a) : "l"(p));
    return a;
}
__device__ __forceinline__ void cpa16(const __nv_bfloat16* s, const __nv_bfloat16* g) {
    uint32_t sa = smem_u32(s);
    asm volatile("cp.async.cg.shared.global [%0], [%1], 16;" :: "r"(sa), "l"(g) : "memory");
}
#define CP_COMMIT() asm volatile("cp.async.commit_group;" ::: "memory")
#define CP_WAIT(n)  asm volatile("cp.async.wait_group %0;" :: "n"(n) : "memory")
// ldmatrix x4 (non-trans): 4 fragment quadrants from 16 row addresses
__device__ __forceinline__ void ldmx4(uint32_t& r0, uint32_t& r1, uint32_t& r2, uint32_t& r3,
                                      uint32_t addr) {
    asm volatile("ldmatrix.sync.aligned.m8n8.x4.shared.b16 {%0,%1,%2,%3}, [%4];"
                 : "=r"(r0), "=r"(r1), "=r"(r2), "=r"(r3) : "r"(addr));
}
// ldmatrix x4 transposed (b16): B-frags from row-major [k][n] memory
__device__ __forceinline__ void ldmx4t(uint32_t& r0, uint32_t& r1, uint32_t& r2, uint32_t& r3,
                                       uint32_t addr) {
    asm volatile("ldmatrix.sync.aligned.m8n8.x4.trans.shared.b16 {%0,%1,%2,%3}, [%4];"
                 : "=r"(r0), "=r"(r1), "=r"(r2), "=r"(r3) : "r"(addr));
}

// ---------------------------------------------------------------------------
// Split fp32 x -> (bf16 hi, bf16 lo)
// ---------------------------------------------------------------------------
__global__ void __launch_bounds__(256) split_kernel(const float* __restrict__ in)
{
    size_t i = ((size_t)blockIdx.x * 256 + threadIdx.x) * 4;
    float4 v = *(const float4*)(in + i);
    __nv_bfloat16 h0 = __float2bfloat16(v.x), h1 = __float2bfloat16(v.y);
    __nv_bfloat16 h2 = __float2bfloat16(v.z), h3 = __float2bfloat16(v.w);
    __nv_bfloat16 l0 = __float2bfloat16(v.x - __bfloat162float(h0));
    __nv_bfloat16 l1 = __float2bfloat16(v.y - __bfloat162float(h1));
    __nv_bfloat16 l2 = __float2bfloat16(v.z - __bfloat162float(h2));
    __nv_bfloat16 l3 = __float2bfloat16(v.w - __bfloat162float(h3));
    *(__nv_bfloat162*)(g_xhi + i)     = __nv_bfloat162(h0, h1);
    *(__nv_bfloat162*)(g_xhi + i + 2) = __nv_bfloat162(h2, h3);
    *(__nv_bfloat162*)(g_xlo + i)     = __nv_bfloat162(l0, l1);
    *(__nv_bfloat162*)(g_xlo + i + 2) = __nv_bfloat162(l2, l3);
}

// ---------------------------------------------------------------------------
// Transpose+split weights: in[K][N] fp32 -> hi/lo [N][K] bf16 (K-major)
// ---------------------------------------------------------------------------
template <int MODE>
__global__ void __launch_bounds__(256) tsplit_kernel(const float* __restrict__ in,
                                                     int Kdim, int Ndim)
{
    __shared__ float tile[32][33];
    const int n0 = blockIdx.x * 32, k0 = blockIdx.y * 32;
    const int tx = threadIdx.x, ty = threadIdx.y;   // (32, 8)
    __nv_bfloat16* hi = (MODE == 0) ? g_wqhi : g_wohi;
    __nv_bfloat16* lo = (MODE == 0) ? g_wqlo : g_wolo;
#pragma unroll
    for (int i = 0; i < 32; i += 8)
        tile[ty + i][tx] = in[(size_t)(k0 + ty + i) * Ndim + n0 + tx];
    __syncthreads();
#pragma unroll
    for (int i = 0; i < 32; i += 8) {
        float v = tile[tx][ty + i];
        __nv_bfloat16 h = __float2bfloat16(v);
        __nv_bfloat16 l = __float2bfloat16(v - __bfloat162float(h));
        size_t o = (size_t)(n0 + ty + i) * Kdim + k0 + tx;
        hi[o] = h;
        lo[o] = l;
    }
}

// ---------------------------------------------------------------------------
// bf16-split HMMA GEMM + bias, 2-stage cp.async pipeline, ldmatrix frags.
// C[M,N] = A[M,1024] @ B[N,1024]^T + bias[N]; 128x128 tile, BK=32, 8 warps.
// MODE 0: A=g_xhi/lo, B=g_wqhi/lo -> g_qkvhi/lo (+bias, bf16 split)
// MODE 1: A=g_chi/lo, B=g_wohi/lo -> fp32 Cext (+bias)
// ---------------------------------------------------------------------------
template <int MODE>
__global__ void __launch_bounds__(256, 2) gemm_hmma_kernel(
    const float* __restrict__ bias, float* __restrict__ Cext, int N)
{
    constexpr int K = 1024;
    constexpr int SA = 40;               // elems; 80B rows (16B-mult, conflict-free ldmatrix)
    constexpr int TS = 128 * SA;         // elems per tile
    extern __shared__ __nv_bfloat16 dsm[];  // [2 stages][Ah|Al|Bh|Bl]

    const __nv_bfloat16* Ahi = (MODE == 0) ? g_xhi : g_chi;
    const __nv_bfloat16* Alo = (MODE == 0) ? g_xlo : g_clo;
    const __nv_bfloat16* Bhi = (MODE == 0) ? g_wqhi : g_wohi;
    const __nv_bfloat16* Blo = (MODE == 0) ? g_wqlo : g_wolo;

    const int tid = threadIdx.x;
    const int wid = tid >> 5, lane = tid & 31;
    const int g = lane >> 2, t2 = (lane & 3) * 2;
    const int warp_m = (wid >> 1) * 32;
    const int warp_n = (wid & 1) * 64;
    const int rowBase = blockIdx.y * 128, colBase = blockIdx.x * 128;

    // ldmatrix per-lane byte offsets (row = lane&15, col-half = (lane>>4)*8)
    const int lmRow = lane & 15, lmK8 = (lane >> 4) * 8;
    uint32_t offA[2], offB[4];
#pragma unroll
    for (int mt = 0; mt < 2; mt++)
        offA[mt] = (uint32_t)(((warp_m + mt * 16 + lmRow) * SA + lmK8) * 2);
#pragma unroll
    for (int np = 0; np < 4; np++)
        offB[np] = (uint32_t)(((warp_n + np * 16 + lmRow) * SA + lmK8) * 2);

    // cp.async coords: 2 chunks of 16B per tile
    const int lrow0 = tid >> 2, lc0 = (tid & 3) * 8;
    const int lrow1 = (tid + 256) >> 2, lc1 = lc0;

    float c[2][8][4];
#pragma unroll
    for (int mt = 0; mt < 2; mt++)
#pragma unroll
        for (int nt = 0; nt < 8; nt++)
#pragma unroll
            for (int j = 0; j < 4; j++) c[mt][nt][j] = 0.0f;

    auto load_stage = [&](int st, int k0) {
        __nv_bfloat16* s = dsm + st * 4 * TS;
        size_t ga0 = (size_t)(rowBase + lrow0) * K + k0 + lc0;
        size_t ga1 = (size_t)(rowBase + lrow1) * K + k0 + lc1;
        size_t gb0 = (size_t)(colBase + lrow0) * K + k0 + lc0;
        size_t gb1 = (size_t)(colBase + lrow1) * K + k0 + lc1;
        cpa16(s + lrow0 * SA + lc0, Ahi + ga0);
        cpa16(s + lrow1 * SA + lc1, Ahi + ga1);
        cpa16(s + TS + lrow0 * SA + lc0, Alo + ga0);
        cpa16(s + TS + lrow1 * SA + lc1, Alo + ga1);
        cpa16(s + 2 * TS + lrow0 * SA + lc0, Bhi + gb0);
        cpa16(s + 2 * TS + lrow1 * SA + lc1, Bhi + gb1);
        cpa16(s + 3 * TS + lrow0 * SA + lc0, Blo + gb0);
        cpa16(s + 3 * TS + lrow1 * SA + lc1, Blo + gb1);
        CP_COMMIT();
    };

    load_stage(0, 0);

    for (int it = 0; it < K / 32; ++it) {
        const int cur = it & 1;
        if (it + 1 < K / 32) {
            load_stage(cur ^ 1, (it + 1) * 32);
            CP_WAIT(1);
        } else {
            CP_WAIT(0);
        }
        __syncthreads();

        const uint32_t sb = smem_u32(dsm + cur * 4 * TS);
        const uint32_t bAl = sb + TS * 2;     // byte offsets of tiles
        const uint32_t bBh = sb + 4 * TS;
        const uint32_t bBl = sb + 6 * TS;

#pragma unroll
        for (int kk = 0; kk < 32; kk += 16) {
            const uint32_t kadd = kk * 2;
            uint32_t ah[2][4], al[2][4];
#pragma unroll
            for (int mt = 0; mt < 2; mt++) {
                ldmx4(ah[mt][0], ah[mt][1], ah[mt][2], ah[mt][3], sb + offA[mt] + kadd);
                ldmx4(al[mt][0], al[mt][1], al[mt][2], al[mt][3], bAl + offA[mt] + kadd);
            }
#pragma unroll
            for (int np = 0; np < 4; np++) {
                uint32_t h0, h1, h2, h3, l0, l1, l2, l3;
                ldmx4(h0, h1, h2, h3, bBh + offB[np] + kadd);
                ldmx4(l0, l1, l2, l3, bBl + offB[np] + kadd);
#pragma unroll
                for (int mt = 0; mt < 2; mt++) {
                    mma_bf16(c[mt][np * 2], ah[mt][0], ah[mt][1], ah[mt][2], ah[mt][3], h0, h2);
                    mma_bf16(c[mt][np * 2], ah[mt][0], ah[mt][1], ah[mt][2], ah[mt][3], l0, l2);
                    mma_bf16(c[mt][np * 2], al[mt][0], al[mt][1], al[mt][2], al[mt][3], h0, h2);
                    mma_bf16(c[mt][np * 2 + 1], ah[mt][0], ah[mt][1], ah[mt][2], ah[mt][3], h1, h3);
                    mma_bf16(c[mt][np * 2 + 1], ah[mt][0], ah[mt][1], ah[mt][2], ah[mt][3], l1, l3);
                    mma_bf16(c[mt][np * 2 + 1], al[mt][0], al[mt][1], al[mt][2], al[mt][3], h1, h3);
                }
            }
        }
        __syncthreads();
    }

    // epilogue
#pragma unroll
    for (int mt = 0; mt < 2; mt++) {
        int row0 = rowBase + warp_m + mt * 16 + g;
        int row1 = row0 + 8;
#pragma unroll
        for (int nt = 0; nt < 8; nt++) {
            int col = colBase + warp_n + nt * 8 + t2;
            float b0 = bias[col], b1 = bias[col + 1];
            float v00 = c[mt][nt][0] + b0, v01 = c[mt][nt][1] + b1;
            float v10 = c[mt][nt][2] + b0, v11 = c[mt][nt][3] + b1;
            if (MODE == 0) {
                __nv_bfloat16 h00 = __float2bfloat16(v00), h01 = __float2bfloat16(v01);
                __nv_bfloat16 h10 = __float2bfloat16(v10), h11 = __float2bfloat16(v11);
                size_t o0 = (size_t)row0 * N + col, o1 = (size_t)row1 * N + col;
                *(__nv_bfloat162*)(g_qkvhi + o0) = __nv_bfloat162(h00, h01);
                *(__nv_bfloat162*)(g_qkvhi + o1) = __nv_bfloat162(h10, h11);
                *(__nv_bfloat162*)(g_qkvlo + o0) = __nv_bfloat162(
                    __float2bfloat16(v00 - __bfloat162float(h00)),
                    __float2bfloat16(v01 - __bfloat162float(h01)));
                *(__nv_bfloat162*)(g_qkvlo + o1) = __nv_bfloat162(
                    __float2bfloat16(v10 - __bfloat162float(h10)),
                    __float2bfloat16(v11 - __bfloat162float(h11)));
            } else {
                *(float2*)(Cext + (size_t)row0 * N + col) = make_float2(v00, v01);
                *(float2*)(Cext + (size_t)row1 * N + col) = make_float2(v10, v11);
            }
        }
    }
}

// ---------------------------------------------------------------------------
// Flash attention on HMMA, 2-stage cp.async pipeline, ldmatrix everywhere.
// Br=128 q-rows/CTA, Bc=64 kv/iter, 8 warps x m16 row-slab. RoPE elided
// (head-indexed tables -> per-head constant orthogonal rotation of q and k).
// ---------------------------------------------------------------------------
__global__ void __launch_bounds__(256, 2) attn_hmma_kernel()
{
    constexpr int SK = 72;              // elems; 144B rows (16B-mult, conflict-free)
    constexpr int KT = 64 * SK;         // elems per tile
    extern __shared__ __nv_bfloat16 dsm[];  // [2 stages][Kh|Kl|Vh|Vl]

    const int bh = blockIdx.x;
    const int b  = bh >> 4, h = bh & 15;
    const int q0 = blockIdx.y * 128;
    const int tid = threadIdx.x;
    const int w = tid >> 5, lane = tid & 31;
    const int g = lane >> 2, t2 = (lane & 3) * 2;

    const int qcol = h * 192, kcol = qcol + 64, vcol = qcol + 128;
    const size_t tokBase = (size_t)b * SEQ;

    // cp.async coords
    const int lrow0 = tid >> 3, lc0 = (tid & 7) * 8;
    const int lrow1 = (tid + 256) >> 3, lc1 = lc0;

    // ldmatrix offsets: K-side (non-trans), V-side (trans)
    const int lmRow = lane & 15, lmK8 = (lane >> 4) * 8;
    uint32_t offK[4];
#pragma unroll
    for (int np = 0; np < 4; np++)
        offK[np] = (uint32_t)(((np * 16 + lmRow) * SK + lmK8) * 2);
    const uint32_t vloff = ((((lane >> 3) & 1) * 8 + (lane & 7)) * SK + (lane >> 4) * 8) * 2;

    // Preload Q a-frags from gmem
    uint32_t qh[4][4], ql[4][4];
    {
        const size_t r0 = (tokBase + q0 + w * 16 + g) * 3072 + qcol;
        const size_t r1 = r0 + (size_t)8 * 3072;
#pragma unroll
        for (int kk = 0; kk < 4; kk++) {
            int cc = kk * 16 + t2;
            qh[kk][0] = lds32(g_qkvhi + r0 + cc);
            qh[kk][1] = lds32(g_qkvhi + r1 + cc);
            qh[kk][2] = lds32(g_qkvhi + r0 + cc + 8);
            qh[kk][3] = lds32(g_qkvhi + r1 + cc + 8);
            ql[kk][0] = lds32(g_qkvlo + r0 + cc);
            ql[kk][1] = lds32(g_qkvlo + r1 + cc);
            ql[kk][2] = lds32(g_qkvlo + r0 + cc + 8);
            ql[kk][3] = lds32(g_qkvlo + r1 + cc + 8);
        }
    }

    float o[8][4];
#pragma unroll
    for (int nt = 0; nt < 8; nt++)
#pragma unroll
        for (int j = 0; j < 4; j++) o[nt][j] = 0.0f;
    float m0 = -INFINITY, m1 = -INFINITY, l0 = 0.0f, l1 = 0.0f;

    auto load_stage = [&](int st, int kv0) {
        __nv_bfloat16* s = dsm + st * 4 * KT;
        size_t gk0 = (tokBase + kv0 + lrow0) * 3072 + kcol + lc0;
        size_t gk1 = (tokBase + kv0 + lrow1) * 3072 + kcol + lc1;
        size_t gv0 = (tokBase + kv0 + lrow0) * 3072 + vcol + lc0;
        size_t gv1 = (tokBase + kv0 + lrow1) * 3072 + vcol + lc1;
        cpa16(s + lrow0 * SK + lc0, g_qkvhi + gk0);
        cpa16(s + lrow1 * SK + lc1, g_qkvhi + gk1);
        cpa16(s + KT + lrow0 * SK + lc0, g_qkvlo + gk0);
        cpa16(s + KT + lrow1 * SK + lc1, g_qkvlo + gk1);
        cpa16(s + 2 * KT + lrow0 * SK + lc0, g_qkvhi + gv0);
        cpa16(s + 2 * KT + lrow1 * SK + lc1, g_qkvhi + gv1);
        cpa16(s + 3 * KT + lrow0 * SK + lc0, g_qkvlo + gv0);
        cpa16(s + 3 * KT + lrow1 * SK + lc1, g_qkvlo + gv1);
        CP_COMMIT();
    };

    load_stage(0, 0);

    for (int it = 0; it < SEQ / 64; ++it) {
        const int cur = it & 1;
        if (it + 1 < SEQ / 64) {
            load_stage(cur ^ 1, (it + 1) * 64);
            CP_WAIT(1);
        } else {
            CP_WAIT(0);
        }
        __syncthreads();

        const uint32_t kb = smem_u32(dsm + cur * 4 * KT);
        const uint32_t kbl = kb + KT * 2;
        const uint32_t vh_base = kb + 4 * KT + vloff;
        const uint32_t vl_base = kb + 6 * KT + vloff;

        // S = Q K^T  (ldmatrix K frags)
        float s[8][4];
#pragma unroll
        for (int nt = 0; nt < 8; nt++)
#pragma unroll
            for (int j = 0; j < 4; j++) s[nt][j] = 0.0f;

#pragma unroll
        for (int kk = 0; kk < 4; kk++) {
            const uint32_t kadd = kk * 32;
#pragma unroll
            for (int np = 0; np < 4; np++) {
                uint32_t h0, h1, h2, h3, l0r, l1r, l2r, l3r;
                ldmx4(h0, h1, h2, h3, kb + offK[np] + kadd);
                ldmx4(l0r, l1r, l2r, l3r, kbl + offK[np] + kadd);
                mma_bf16(s[np * 2], qh[kk][0], qh[kk][1], qh[kk][2], qh[kk][3], h0, h2);
                mma_bf16(s[np * 2], qh[kk][0], qh[kk][1], qh[kk][2], qh[kk][3], l0r, l2r);
                mma_bf16(s[np * 2], ql[kk][0], ql[kk][1], ql[kk][2], ql[kk][3], h0, h2);
                mma_bf16(s[np * 2 + 1], qh[kk][0], qh[kk][1], qh[kk][2], qh[kk][3], h1, h3);
                mma_bf16(s[np * 2 + 1], qh[kk][0], qh[kk][1], qh[kk][2], qh[kk][3], l1r, l3r);
                mma_bf16(s[np * 2 + 1], ql[kk][0], ql[kk][1], ql[kk][2], ql[kk][3], h1, h3);
            }
        }

        // online softmax
        float mt0 = -INFINITY, mt1 = -INFINITY;
#pragma unroll
        for (int nt = 0; nt < 8; nt++) {
#pragma unroll
            for (int j = 0; j < 4; j++) s[nt][j] *= 0.125f;
            mt0 = fmaxf(mt0, fmaxf(s[nt][0], s[nt][1]));
            mt1 = fmaxf(mt1, fmaxf(s[nt][2], s[nt][3]));
        }
        mt0 = fmaxf(mt0, __shfl_xor_sync(0xffffffffu, mt0, 1, 4));
        mt0 = fmaxf(mt0, __shfl_xor_sync(0xffffffffu, mt0, 2, 4));
        mt1 = fmaxf(mt1, __shfl_xor_sync(0xffffffffu, mt1, 1, 4));
        mt1 = fmaxf(mt1, __shfl_xor_sync(0xffffffffu, mt1, 2, 4));
        float mn0 = fmaxf(m0, mt0), mn1 = fmaxf(m1, mt1);
        float a0 = __expf(m0 - mn0), a1 = __expf(m1 - mn1);
        float ls0 = 0.0f, ls1 = 0.0f;
#pragma unroll
        for (int nt = 0; nt < 8; nt++) {
            s[nt][0] = __expf(s[nt][0] - mn0);
            s[nt][1] = __expf(s[nt][1] - mn0);
            s[nt][2] = __expf(s[nt][2] - mn1);
            s[nt][3] = __expf(s[nt][3] - mn1);
            ls0 += s[nt][0] + s[nt][1];
            ls1 += s[nt][2] + s[nt][3];
        }
        ls0 += __shfl_xor_sync(0xffffffffu, ls0, 1, 4);
        ls0 += __shfl_xor_sync(0xffffffffu, ls0, 2, 4);
        ls1 += __shfl_xor_sync(0xffffffffu, ls1, 1, 4);
        ls1 += __shfl_xor_sync(0xffffffffu, ls1, 2, 4);
        l0 = l0 * a0 + ls0;
        l1 = l1 * a1 + ls1;
        m0 = mn0;
        m1 = mn1;
#pragma unroll
        for (int nt = 0; nt < 8; nt++) {
            o[nt][0] *= a0;
            o[nt][1] *= a0;
            o[nt][2] *= a1;
            o[nt][3] *= a1;
        }

        // P -> a-frags (hi/lo) via c-frag identity
        uint32_t ph[4][4], pl[4][4];
#pragma unroll
        for (int kt = 0; kt < 4; kt++) {
            float p00 = s[kt * 2][0],     p01 = s[kt * 2][1];
            float p10 = s[kt * 2][2],     p11 = s[kt * 2][3];
            float p20 = s[kt * 2 + 1][0], p21 = s[kt * 2 + 1][1];
            float p30 = s[kt * 2 + 1][2], p31 = s[kt * 2 + 1][3];
            ph[kt][0] = pack_bf16(p00, p01);
            ph[kt][1] = pack_bf16(p10, p11);
            ph[kt][2] = pack_bf16(p20, p21);
            ph[kt][3] = pack_bf16(p30, p31);
            const __nv_bfloat162* hp;
            hp = (const __nv_bfloat162*)&ph[kt][0];
            pl[kt][0] = pack_bf16(p00 - __bfloat162float(hp->x), p01 - __bfloat162float(hp->y));
            hp = (const __nv_bfloat162*)&ph[kt][1];
            pl[kt][1] = pack_bf16(p10 - __bfloat162float(hp->x), p11 - __bfloat162float(hp->y));
            hp = (const __nv_bfloat162*)&ph[kt][2];
            pl[kt][2] = pack_bf16(p20 - __bfloat162float(hp->x), p21 - __bfloat162float(hp->y));
            hp = (const __nv_bfloat162*)&ph[kt][3];
            pl[kt][3] = pack_bf16(p30 - __bfloat162float(hp->x), p31 - __bfloat162float(hp->y));
        }

        // O += P V : B-frags from natural V layout via ldmatrix.trans
#pragma unroll
        for (int np = 0; np < 4; np++) {
#pragma unroll
            for (int kt = 0; kt < 4; kt++) {
                uint32_t off = (uint32_t)((kt * 16 * SK + np * 16) * 2);
                uint32_t bh0, bh1, bh2, bh3, bl0, bl1, bl2, bl3;
                ldmx4t(bh0, bh1, bh2, bh3, vh_base + off);
                ldmx4t(bl0, bl1, bl2, bl3, vl_base + off);
                mma_bf16(o[np * 2], ph[kt][0], ph[kt][1], ph[kt][2], ph[kt][3], bh0, bh1);
                mma_bf16(o[np * 2], ph[kt][0], ph[kt][1], ph[kt][2], ph[kt][3], bl0, bl1);
                mma_bf16(o[np * 2], pl[kt][0], pl[kt][1], pl[kt][2], pl[kt][3], bh0, bh1);
                mma_bf16(o[np * 2 + 1], ph[kt][0], ph[kt][1], ph[kt][2], ph[kt][3], bh2, bh3);
                mma_bf16(o[np * 2 + 1], ph[kt][0], ph[kt][1], ph[kt][2], ph[kt][3], bl2, bl3);
                mma_bf16(o[np * 2 + 1], pl[kt][0], pl[kt][1], pl[kt][2], pl[kt][3], bh2, bh3);
            }
        }
        __syncthreads();
    }

    // epilogue: normalize, split to bf16 hi/lo, write ctx
    const float i0 = 1.0f / l0, i1 = 1.0f / l1;
    const size_t c0 = (tokBase + q0 + w * 16 + g) * HIDDEN + h * HD;
    const size_t c1 = c0 + (size_t)8 * HIDDEN;
#pragma unroll
    for (int nt = 0; nt < 8; nt++) {
        int d = nt * 8 + t2;
        float v00 = o[nt][0] * i0, v01 = o[nt][1] * i0;
        float v10 = o[nt][2] * i1, v11 = o[nt][3] * i1;
        __nv_bfloat16 h00 = __float2bfloat16(v00), h01 = __float2bfloat16(v01);
        __nv_bfloat16 h10 = __float2bfloat16(v10), h11 = __float2bfloat16(v11);
        *(__nv_bfloat162*)(g_chi + c0 + d) = __nv_bfloat162(h00, h01);
        *(__nv_bfloat162*)(g_chi + c1 + d) = __nv_bfloat162(h10, h11);
        *(__nv_bfloat162*)(g_clo + c0 + d) = __nv_bfloat162(
            __float2bfloat16(v00 - __bfloat162float(h00)),
            __float2bfloat16(v01 - __bfloat162float(h01)));
        *(__nv_bfloat162*)(g_clo + c1 + d) = __nv_bfloat162(
            __float2bfloat16(v10 - __bfloat162float(h10)),
            __float2bfloat16(v11 - __bfloat162float(h11)));
    }
}

// ---------------------------------------------------------------------------
extern "C" void kernel_launch(void* const* d_in, const int* in_sizes, int n_in,
                              void* d_out, int out_size)
{
    (void)in_sizes; (void)n_in; (void)out_size;
    const float* x     = (const float*)d_in[0];
    const float* qkv_w = (const float*)d_in[1];
    const float* qkv_b = (const float*)d_in[2];
    const float* out_w = (const float*)d_in[3];
    const float* out_b = (const float*)d_in[4];
    float* out = (float*)d_out;

    const int gemm_smem = 2 * 4 * 128 * 40 * 2;   // 81920 B
    const int attn_smem = 2 * 4 * 64 * 72 * 2;    // 73728 B
    cudaFuncSetAttribute(gemm_hmma_kernel<0>, cudaFuncAttributeMaxDynamicSharedMemorySize, gemm_smem);
    cudaFuncSetAttribute(gemm_hmma_kernel<1>, cudaFuncAttributeMaxDynamicSharedMemorySize, gemm_smem);
    cudaFuncSetAttribute(attn_hmma_kernel, cudaFuncAttributeMaxDynamicSharedMemorySize, attn_smem);

    // 0) splits
    tsplit_kernel<0><<<dim3(3 * HIDDEN / 32, HIDDEN / 32), dim3(32, 8)>>>(qkv_w, HIDDEN, 3 * HIDDEN);
    tsplit_kernel<1><<<dim3(HIDDEN / 32, HIDDEN / 32), dim3(32, 8)>>>(out_w, HIDDEN, HIDDEN);
    split_kernel<<<(MROWS * HIDDEN) / (256 * 4), 256>>>(x);

    // 1) QKV projection -> bf16 hi/lo qkv
    gemm_hmma_kernel<0><<<dim3(3 * HIDDEN / 128, MROWS / 128), 256, gemm_smem>>>(
        qkv_b, nullptr, 3 * HIDDEN);

    // 2) Flash attention -> bf16 hi/lo ctx
    attn_hmma_kernel<<<dim3(BATCH * HEADS, SEQ / 128), 256, attn_smem>>>();

    // 3) Output projection -> fp32 out
    gemm_hmma_kernel<1><<<dim3(HIDDEN / 128, MROWS / 128), 256, gemm_smem>>>(
        out_b, out, HIDDEN);
}

// round 17
// speedup vs baseline: 1.7155x; 1.7155x over previous
#include <cuda_runtime.h>
#include <cuda_bf16.h>
#include <math.h>
#include <stdint.h>

#define HIDDEN 1024
#define SEQ    2048
#define BATCH  2
#define HEADS  16
#define HD     64
#define MROWS  (BATCH * SEQ)   /* 4096 */

// ---------------------------------------------------------------------------
// Scratch (device globals — no allocation allowed)
// ---------------------------------------------------------------------------
__device__ __align__(16) __nv_bfloat16 g_xhi[(size_t)MROWS * HIDDEN];
__device__ __align__(16) __nv_bfloat16 g_xlo[(size_t)MROWS * HIDDEN];
__device__ __align__(16) __nv_bfloat16 g_qkvhi[(size_t)MROWS * 3 * HIDDEN]; // [4096][3072]
__device__ __align__(16) __nv_bfloat16 g_qkvlo[(size_t)MROWS * 3 * HIDDEN];
__device__ __align__(16) __nv_bfloat16 g_chi[(size_t)MROWS * HIDDEN];
__device__ __align__(16) __nv_bfloat16 g_clo[(size_t)MROWS * HIDDEN];
__device__ __align__(16) __nv_bfloat16 g_wqhi[(size_t)3 * HIDDEN * HIDDEN]; // [3072][1024] K-major
__device__ __align__(16) __nv_bfloat16 g_wqlo[(size_t)3 * HIDDEN * HIDDEN];
__device__ __align__(16) __nv_bfloat16 g_wohi[(size_t)HIDDEN * HIDDEN];     // [1024][1024] K-major
__device__ __align__(16) __nv_bfloat16 g_wolo[(size_t)HIDDEN * HIDDEN];

// ---------------------------------------------------------------------------
// helpers
// ---------------------------------------------------------------------------
__device__ __forceinline__ void mma_bf16(float c[4],
                                         uint32_t a0, uint32_t a1, uint32_t a2, uint32_t a3,
                                         uint32_t b0, uint32_t b1) {
    asm volatile(
        "mma.sync.aligned.m16n8k16.row.col.f32.bf16.bf16.f32 "
        "{%0,%1,%2,%3}, {%4,%5,%6,%7}, {%8,%9}, {%0,%1,%2,%3};"
        : "+f"(c[0]), "+f"(c[1]), "+f"(c[2]), "+f"(c[3])
        : "r"(a0), "r"(a1), "r"(a2), "r"(a3), "r"(b0), "r"(b1));
}
__device__ __forceinline__ uint32_t pack_bf16(float x, float y) {
    __nv_bfloat162 t = __floats2bfloat162_rn(x, y);
    return *(uint32_t*)&t;
}
__device__ __forceinline__ uint32_t lds32(const __nv_bfloat16* p) {
    return *(const uint32_t*)p;
}
__device__ __forceinline__ uint32_t smem_u32(const void* p) {
    uint32_t a;
    asm("{ .reg .u64 t; cvta.to.shared.u64 t, %1; cvt.u32.u64 %0, t; }" : "=r"(a) : "l"(p));
    return a;
}
__device__ __forceinline__ void cpa16(const __nv_bfloat16* s, const __nv_bfloat16* g) {
    uint32_t sa = smem_u32(s);
    asm volatile("cp.async.cg.shared.global [%0], [%1], 16;" :: "r"(sa), "l"(g) : "memory");
}
#define CP_COMMIT() asm volatile("cp.async.commit_group;" ::: "memory")
#define CP_WAIT(n)  asm volatile("cp.async.wait_group %0;" :: "n"(n) : "memory")
// ldmatrix x4 transposed (b16): B-frags from row-major [k][n] memory
__device__ __forceinline__ void ldmx4t(uint32_t& r0, uint32_t& r1, uint32_t& r2, uint32_t& r3,
                                       uint32_t addr) {
    asm volatile("ldmatrix.sync.aligned.m8n8.x4.trans.shared.b16 {%0,%1,%2,%3}, [%4];"
                 : "=r"(r0), "=r"(r1), "=r"(r2), "=r"(r3) : "r"(addr));
}

// ---------------------------------------------------------------------------
// Split fp32 x -> (bf16 hi, bf16 lo)
// ---------------------------------------------------------------------------
__global__ void __launch_bounds__(256) split_kernel(const float* __restrict__ in)
{
    size_t i = ((size_t)blockIdx.x * 256 + threadIdx.x) * 4;
    float4 v = *(const float4*)(in + i);
    __nv_bfloat16 h0 = __float2bfloat16(v.x), h1 = __float2bfloat16(v.y);
    __nv_bfloat16 h2 = __float2bfloat16(v.z), h3 = __float2bfloat16(v.w);
    __nv_bfloat16 l0 = __float2bfloat16(v.x - __bfloat162float(h0));
    __nv_bfloat16 l1 = __float2bfloat16(v.y - __bfloat162float(h1));
    __nv_bfloat16 l2 = __float2bfloat16(v.z - __bfloat162float(h2));
    __nv_bfloat16 l3 = __float2bfloat16(v.w - __bfloat162float(h3));
    *(__nv_bfloat162*)(g_xhi + i)     = __nv_bfloat162(h0, h1);
    *(__nv_bfloat162*)(g_xhi + i + 2) = __nv_bfloat162(h2, h3);
    *(__nv_bfloat162*)(g_xlo + i)     = __nv_bfloat162(l0, l1);
    *(__nv_bfloat162*)(g_xlo + i + 2) = __nv_bfloat162(l2, l3);
}

// ---------------------------------------------------------------------------
// Transpose+split weights: in[K][N] fp32 -> hi/lo [N][K] bf16 (K-major)
// ---------------------------------------------------------------------------
template <int MODE>
__global__ void __launch_bounds__(256) tsplit_kernel(const float* __restrict__ in,
                                                     int Kdim, int Ndim)
{
    __shared__ float tile[32][33];
    const int n0 = blockIdx.x * 32, k0 = blockIdx.y * 32;
    const int tx = threadIdx.x, ty = threadIdx.y;   // (32, 8)
    __nv_bfloat16* hi = (MODE == 0) ? g_wqhi : g_wohi;
    __nv_bfloat16* lo = (MODE == 0) ? g_wqlo : g_wolo;
#pragma unroll
    for (int i = 0; i < 32; i += 8)
        tile[ty + i][tx] = in[(size_t)(k0 + ty + i) * Ndim + n0 + tx];
    __syncthreads();
#pragma unroll
    for (int i = 0; i < 32; i += 8) {
        float v = tile[tx][ty + i];
        __nv_bfloat16 h = __float2bfloat16(v);
        __nv_bfloat16 l = __float2bfloat16(v - __bfloat162float(h));
        size_t o = (size_t)(n0 + ty + i) * Kdim + k0 + tx;
        hi[o] = h;
        lo[o] = l;
    }
}

// ---------------------------------------------------------------------------
// bf16-split HMMA GEMM + bias, 2-stage cp.async pipeline, 64x64 warp tile.
// C[M,N] = A[M,1024] @ B[N,1024]^T + bias[N]; 128x128 tile, BK=32,
// 4 warps (2x2 of 64x64) -> 85 B smem traffic per MMA (vs 128 B at 32x64),
// so the crossbar no longer co-saturates with the tensor pipe.
// MODE 0: A=g_xhi/lo, B=g_wqhi/lo -> g_qkvhi/lo (+bias, bf16 split)
// MODE 1: A=g_chi/lo, B=g_wohi/lo -> fp32 Cext (+bias)
// ---------------------------------------------------------------------------
template <int MODE>
__global__ void __launch_bounds__(128, 2) gemm_hmma_kernel(
    const float* __restrict__ bias, float* __restrict__ Cext, int N)
{
    constexpr int K = 1024;
    constexpr int SA = 40;               // elems; 80B rows
    constexpr int TS = 128 * SA;         // elems per tile
    extern __shared__ __nv_bfloat16 dsm[];  // [2 stages][Ah|Al|Bh|Bl]

    const __nv_bfloat16* Ahi = (MODE == 0) ? g_xhi : g_chi;
    const __nv_bfloat16* Alo = (MODE == 0) ? g_xlo : g_clo;
    const __nv_bfloat16* Bhi = (MODE == 0) ? g_wqhi : g_wohi;
    const __nv_bfloat16* Blo = (MODE == 0) ? g_wqlo : g_wolo;

    const int tid = threadIdx.x;
    const int wid = tid >> 5, lane = tid & 31;
    const int g = lane >> 2, t2 = (lane & 3) * 2;
    const int warp_m = (wid >> 1) * 64;      // 0 or 64
    const int warp_n = (wid & 1) * 64;       // 0 or 64
    const int rowBase = blockIdx.y * 128, colBase = blockIdx.x * 128;

    float c[4][8][4];
#pragma unroll
    for (int mt = 0; mt < 4; mt++)
#pragma unroll
        for (int nt = 0; nt < 8; nt++)
#pragma unroll
            for (int j = 0; j < 4; j++) c[mt][nt][j] = 0.0f;

    // loader: 512 16B-chunks per tile / 128 threads = 4 chunks per thread
    auto load_stage = [&](int st, int k0) {
        __nv_bfloat16* s = dsm + st * 4 * TS;
#pragma unroll
        for (int t = 0; t < 4; t++) {
            int i = tid + t * 128;
            int row = i >> 2;
            int col = (i & 3) * 8;
            size_t ga = (size_t)(rowBase + row) * K + k0 + col;
            size_t gb = (size_t)(colBase + row) * K + k0 + col;
            cpa16(s + row * SA + col, Ahi + ga);
            cpa16(s + TS + row * SA + col, Alo + ga);
            cpa16(s + 2 * TS + row * SA + col, Bhi + gb);
            cpa16(s + 3 * TS + row * SA + col, Blo + gb);
        }
        CP_COMMIT();
    };

    load_stage(0, 0);

    for (int it = 0; it < K / 32; ++it) {
        const int cur = it & 1;
        if (it + 1 < K / 32) {
            load_stage(cur ^ 1, (it + 1) * 32);
            CP_WAIT(1);
        } else {
            CP_WAIT(0);
        }
        __syncthreads();

        const __nv_bfloat16* sAh = dsm + cur * 4 * TS;
        const __nv_bfloat16* sAl = sAh + TS;
        const __nv_bfloat16* sBh = sAh + 2 * TS;
        const __nv_bfloat16* sBl = sAh + 3 * TS;

#pragma unroll
        for (int kk = 0; kk < 32; kk += 16) {
            uint32_t ah[4][4], al[4][4];
#pragma unroll
            for (int mt = 0; mt < 4; mt++) {
                int r0 = (warp_m + mt * 16 + g) * SA;
                int r1 = r0 + 8 * SA;
                ah[mt][0] = lds32(&sAh[r0 + kk + t2]);
                ah[mt][1] = lds32(&sAh[r1 + kk + t2]);
                ah[mt][2] = lds32(&sAh[r0 + kk + 8 + t2]);
                ah[mt][3] = lds32(&sAh[r1 + kk + 8 + t2]);
                al[mt][0] = lds32(&sAl[r0 + kk + t2]);
                al[mt][1] = lds32(&sAl[r1 + kk + t2]);
                al[mt][2] = lds32(&sAl[r0 + kk + 8 + t2]);
                al[mt][3] = lds32(&sAl[r1 + kk + 8 + t2]);
            }
#pragma unroll
            for (int nt = 0; nt < 8; nt++) {
                int nr = (warp_n + nt * 8 + g) * SA;
                uint32_t bh0 = lds32(&sBh[nr + kk + t2]);
                uint32_t bh1 = lds32(&sBh[nr + kk + 8 + t2]);
                uint32_t bl0 = lds32(&sBl[nr + kk + t2]);
                uint32_t bl1 = lds32(&sBl[nr + kk + 8 + t2]);
#pragma unroll
                for (int mt = 0; mt < 4; mt++) {
                    mma_bf16(c[mt][nt], ah[mt][0], ah[mt][1], ah[mt][2], ah[mt][3], bh0, bh1);
                    mma_bf16(c[mt][nt], ah[mt][0], ah[mt][1], ah[mt][2], ah[mt][3], bl0, bl1);
                    mma_bf16(c[mt][nt], al[mt][0], al[mt][1], al[mt][2], al[mt][3], bh0, bh1);
                }
            }
        }
        __syncthreads();
    }

    // epilogue
#pragma unroll
    for (int mt = 0; mt < 4; mt++) {
        int row0 = rowBase + warp_m + mt * 16 + g;
        int row1 = row0 + 8;
#pragma unroll
        for (int nt = 0; nt < 8; nt++) {
            int col = colBase + warp_n + nt * 8 + t2;
            float b0 = bias[col], b1 = bias[col + 1];
            float v00 = c[mt][nt][0] + b0, v01 = c[mt][nt][1] + b1;
            float v10 = c[mt][nt][2] + b0, v11 = c[mt][nt][3] + b1;
            if (MODE == 0) {
                __nv_bfloat16 h00 = __float2bfloat16(v00), h01 = __float2bfloat16(v01);
                __nv_bfloat16 h10 = __float2bfloat16(v10), h11 = __float2bfloat16(v11);
                size_t o0 = (size_t)row0 * N + col, o1 = (size_t)row1 * N + col;
                *(__nv_bfloat162*)(g_qkvhi + o0) = __nv_bfloat162(h00, h01);
                *(__nv_bfloat162*)(g_qkvhi + o1) = __nv_bfloat162(h10, h11);
                *(__nv_bfloat162*)(g_qkvlo + o0) = __nv_bfloat162(
                    __float2bfloat16(v00 - __bfloat162float(h00)),
                    __float2bfloat16(v01 - __bfloat162float(h01)));
                *(__nv_bfloat162*)(g_qkvlo + o1) = __nv_bfloat162(
                    __float2bfloat16(v10 - __bfloat162float(h10)),
                    __float2bfloat16(v11 - __bfloat162float(h11)));
            } else {
                *(float2*)(Cext + (size_t)row0 * N + col) = make_float2(v00, v01);
                *(float2*)(Cext + (size_t)row1 * N + col) = make_float2(v10, v11);
            }
        }
    }
}

// ---------------------------------------------------------------------------
// Flash attention on HMMA (exact R10 version — best known).
// Br=128 q-rows/CTA, Bc=64 kv/iter, 8 warps x m16 row-slab. RoPE elided
// (head-indexed tables -> per-head constant orthogonal rotation of q and k).
// ---------------------------------------------------------------------------
__global__ void __launch_bounds__(256, 2) attn_hmma_kernel()
{
    constexpr int SK = 72;              // elems; 144B rows, 16B-aligned
    constexpr int KT = 64 * SK;         // elems per tile
    extern __shared__ __nv_bfloat16 dsm[];  // [2 stages][Kh|Kl|Vh|Vl]

    const int bh = blockIdx.x;
    const int b  = bh >> 4, h = bh & 15;
    const int q0 = blockIdx.y * 128;
    const int tid = threadIdx.x;
    const int w = tid >> 5, lane = tid & 31;
    const int g = lane >> 2, t2 = (lane & 3) * 2;

    const int qcol = h * 192, kcol = qcol + 64, vcol = qcol + 128;
    const size_t tokBase = (size_t)b * SEQ;

    const int lrow0 = tid >> 3, lc0 = (tid & 7) * 8;
    const int lrow1 = (tid + 256) >> 3, lc1 = lc0;

    const uint32_t vloff = ((((lane >> 3) & 1) * 8 + (lane & 7)) * SK + (lane >> 4) * 8) * 2;

    uint32_t qh[4][4], ql[4][4];
    {
        const size_t r0 = (tokBase + q0 + w * 16 + g) * 3072 + qcol;
        const size_t r1 = r0 + (size_t)8 * 3072;
#pragma unroll
        for (int kk = 0; kk < 4; kk++) {
            int cc = kk * 16 + t2;
            qh[kk][0] = lds32(g_qkvhi + r0 + cc);
            qh[kk][1] = lds32(g_qkvhi + r1 + cc);
            qh[kk][2] = lds32(g_qkvhi + r0 + cc + 8);
            qh[kk][3] = lds32(g_qkvhi + r1 + cc + 8);
            ql[kk][0] = lds32(g_qkvlo + r0 + cc);
            ql[kk][1] = lds32(g_qkvlo + r1 + cc);
            ql[kk][2] = lds32(g_qkvlo + r0 + cc + 8);
            ql[kk][3] = lds32(g_qkvlo + r1 + cc + 8);
        }
    }

    float o[8][4];
#pragma unroll
    for (int nt = 0; nt < 8; nt++)
#pragma unroll
        for (int j = 0; j < 4; j++) o[nt][j] = 0.0f;
    float m0 = -INFINITY, m1 = -INFINITY, l0 = 0.0f, l1 = 0.0f;

    auto load_stage = [&](int st, int kv0) {
        __nv_bfloat16* s = dsm + st * 4 * KT;
        size_t gk0 = (tokBase + kv0 + lrow0) * 3072 + kcol + lc0;
        size_t gk1 = (tokBase + kv0 + lrow1) * 3072 + kcol + lc1;
        size_t gv0 = (tokBase + kv0 + lrow0) * 3072 + vcol + lc0;
        size_t gv1 = (tokBase + kv0 + lrow1) * 3072 + vcol + lc1;
        cpa16(s + lrow0 * SK + lc0, g_qkvhi + gk0);
        cpa16(s + lrow1 * SK + lc1, g_qkvhi + gk1);
        cpa16(s + KT + lrow0 * SK + lc0, g_qkvlo + gk0);
        cpa16(s + KT + lrow1 * SK + lc1, g_qkvlo + gk1);
        cpa16(s + 2 * KT + lrow0 * SK + lc0, g_qkvhi + gv0);
        cpa16(s + 2 * KT + lrow1 * SK + lc1, g_qkvhi + gv1);
        cpa16(s + 3 * KT + lrow0 * SK + lc0, g_qkvlo + gv0);
        cpa16(s + 3 * KT + lrow1 * SK + lc1, g_qkvlo + gv1);
        CP_COMMIT();
    };

    load_stage(0, 0);

    for (int it = 0; it < SEQ / 64; ++it) {
        const int cur = it & 1;
        if (it + 1 < SEQ / 64) {
            load_stage(cur ^ 1, (it + 1) * 64);
            CP_WAIT(1);
        } else {
            CP_WAIT(0);
        }
        __syncthreads();

        const __nv_bfloat16* Kh = dsm + cur * 4 * KT;
        const __nv_bfloat16* Kl = Kh + KT;
        const uint32_t vh_base = smem_u32(Kh + 2 * KT) + vloff;
        const uint32_t vl_base = smem_u32(Kh + 3 * KT) + vloff;

        float s[8][4];
#pragma unroll
        for (int nt = 0; nt < 8; nt++) {
#pragma unroll
            for (int j = 0; j < 4; j++) s[nt][j] = 0.0f;
            int nr = (nt * 8 + g) * SK;
#pragma unroll
            for (int kk = 0; kk < 4; kk++) {
                int cc = kk * 16 + t2;
                uint32_t bh0 = lds32(&Kh[nr + cc]);
                uint32_t bh1 = lds32(&Kh[nr + cc + 8]);
                uint32_t bl0 = lds32(&Kl[nr + cc]);
                uint32_t bl1 = lds32(&Kl[nr + cc + 8]);
                mma_bf16(s[nt], qh[kk][0], qh[kk][1], qh[kk][2], qh[kk][3], bh0, bh1);
                mma_bf16(s[nt], qh[kk][0], qh[kk][1], qh[kk][2], qh[kk][3], bl0, bl1);
                mma_bf16(s[nt], ql[kk][0], ql[kk][1], ql[kk][2], ql[kk][3], bh0, bh1);
            }
        }

        float mt0 = -INFINITY, mt1 = -INFINITY;
#pragma unroll
        for (int nt = 0; nt < 8; nt++) {
#pragma unroll
            for (int j = 0; j < 4; j++) s[nt][j] *= 0.125f;
            mt0 = fmaxf(mt0, fmaxf(s[nt][0], s[nt][1]));
            mt1 = fmaxf(mt1, fmaxf(s[nt][2], s[nt][3]));
        }
        mt0 = fmaxf(mt0, __shfl_xor_sync(0xffffffffu, mt0, 1, 4));
        mt0 = fmaxf(mt0, __shfl_xor_sync(0xffffffffu, mt0, 2, 4));
        mt1 = fmaxf(mt1, __shfl_xor_sync(0xffffffffu, mt1, 1, 4));
        mt1 = fmaxf(mt1, __shfl_xor_sync(0xffffffffu, mt1, 2, 4));
        float mn0 = fmaxf(m0, mt0), mn1 = fmaxf(m1, mt1);
        float a0 = __expf(m0 - mn0), a1 = __expf(m1 - mn1);
        float ls0 = 0.0f, ls1 = 0.0f;
#pragma unroll
        for (int nt = 0; nt < 8; nt++) {
            s[nt][0] = __expf(s[nt][0] - mn0);
            s[nt][1] = __expf(s[nt][1] - mn0);
            s[nt][2] = __expf(s[nt][2] - mn1);
            s[nt][3] = __expf(s[nt][3] - mn1);
            ls0 += s[nt][0] + s[nt][1];
            ls1 += s[nt][2] + s[nt][3];
        }
        ls0 += __shfl_xor_sync(0xffffffffu, ls0, 1, 4);
        ls0 += __shfl_xor_sync(0xffffffffu, ls0, 2, 4);
        ls1 += __shfl_xor_sync(0xffffffffu, ls1, 1, 4);
        ls1 += __shfl_xor_sync(0xffffffffu, ls1, 2, 4);
        l0 = l0 * a0 + ls0;
        l1 = l1 * a1 + ls1;
        m0 = mn0;
        m1 = mn1;
#pragma unroll
        for (int nt = 0; nt < 8; nt++) {
            o[nt][0] *= a0;
            o[nt][1] *= a0;
            o[nt][2] *= a1;
            o[nt][3] *= a1;
        }

        uint32_t ph[4][4], pl[4][4];
#pragma unroll
        for (int kt = 0; kt < 4; kt++) {
            float p00 = s[kt * 2][0],     p01 = s[kt * 2][1];
            float p10 = s[kt * 2][2],     p11 = s[kt * 2][3];
            float p20 = s[kt * 2 + 1][0], p21 = s[kt * 2 + 1][1];
            float p30 = s[kt * 2 + 1][2], p31 = s[kt * 2 + 1][3];
            ph[kt][0] = pack_bf16(p00, p01);
            ph[kt][1] = pack_bf16(p10, p11);
            ph[kt][2] = pack_bf16(p20, p21);
            ph[kt][3] = pack_bf16(p30, p31);
            const __nv_bfloat162* hp;
            hp = (const __nv_bfloat162*)&ph[kt][0];
            pl[kt][0] = pack_bf16(p00 - __bfloat162float(hp->x), p01 - __bfloat162float(hp->y));
            hp = (const __nv_bfloat162*)&ph[kt][1];
            pl[kt][1] = pack_bf16(p10 - __bfloat162float(hp->x), p11 - __bfloat162float(hp->y));
            hp = (const __nv_bfloat162*)&ph[kt][2];
            pl[kt][2] = pack_bf16(p20 - __bfloat162float(hp->x), p21 - __bfloat162float(hp->y));
            hp = (const __nv_bfloat162*)&ph[kt][3];
            pl[kt][3] = pack_bf16(p30 - __bfloat162float(hp->x), p31 - __bfloat162float(hp->y));
        }

#pragma unroll
        for (int np = 0; np < 4; np++) {
#pragma unroll
            for (int kt = 0; kt < 4; kt++) {
                uint32_t off = (uint32_t)((kt * 16 * SK + np * 16) * 2);
                uint32_t bh0, bh1, bh2, bh3, bl0, bl1, bl2, bl3;
                ldmx4t(bh0, bh1, bh2, bh3, vh_base + off);
                ldmx4t(bl0, bl1, bl2, bl3, vl_base + off);
                mma_bf16(o[np * 2], ph[kt][0], ph[kt][1], ph[kt][2], ph[kt][3], bh0, bh1);
                mma_bf16(o[np * 2], ph[kt][0], ph[kt][1], ph[kt][2], ph[kt][3], bl0, bl1);
                mma_bf16(o[np * 2], pl[kt][0], pl[kt][1], pl[kt][2], pl[kt][3], bh0, bh1);
                mma_bf16(o[np * 2 + 1], ph[kt][0], ph[kt][1], ph[kt][2], ph[kt][3], bh2, bh3);
                mma_bf16(o[np * 2 + 1], ph[kt][0], ph[kt][1], ph[kt][2], ph[kt][3], bl2, bl3);
                mma_bf16(o[np * 2 + 1], pl[kt][0], pl[kt][1], pl[kt][2], pl[kt][3], bh2, bh3);
            }
        }
        __syncthreads();
    }

    const float i0 = 1.0f / l0, i1 = 1.0f / l1;
    const size_t c0 = (tokBase + q0 + w * 16 + g) * HIDDEN + h * HD;
    const size_t c1 = c0 + (size_t)8 * HIDDEN;
#pragma unroll
    for (int nt = 0; nt < 8; nt++) {
        int d = nt * 8 + t2;
        float v00 = o[nt][0] * i0, v01 = o[nt][1] * i0;
        float v10 = o[nt][2] * i1, v11 = o[nt][3] * i1;
        __nv_bfloat16 h00 = __float2bfloat16(v00), h01 = __float2bfloat16(v01);
        __nv_bfloat16 h10 = __float2bfloat16(v10), h11 = __float2bfloat16(v11);
        *(__nv_bfloat162*)(g_chi + c0 + d) = __nv_bfloat162(h00, h01);
        *(__nv_bfloat162*)(g_chi + c1 + d) = __nv_bfloat162(h10, h11);
        *(__nv_bfloat162*)(g_clo + c0 + d) = __nv_bfloat162(
            __float2bfloat16(v00 - __bfloat162float(h00)),
            __float2bfloat16(v01 - __bfloat162float(h01)));
        *(__nv_bfloat162*)(g_clo + c1 + d) = __nv_bfloat162(
            __float2bfloat16(v10 - __bfloat162float(h10)),
            __float2bfloat16(v11 - __bfloat162float(h11)));
    }
}

// ---------------------------------------------------------------------------
extern "C" void kernel_launch(void* const* d_in, const int* in_sizes, int n_in,
                              void* d_out, int out_size)
{
    (void)in_sizes; (void)n_in; (void)out_size;
    const float* x     = (const float*)d_in[0];
    const float* qkv_w = (const float*)d_in[1];
    const float* qkv_b = (const float*)d_in[2];
    const float* out_w = (const float*)d_in[3];
    const float* out_b = (const float*)d_in[4];
    float* out = (float*)d_out;

    const int gemm_smem = 2 * 4 * 128 * 40 * 2;   // 81920 B
    const int attn_smem = 2 * 4 * 64 * 72 * 2;    // 73728 B
    cudaFuncSetAttribute(gemm_hmma_kernel<0>, cudaFuncAttributeMaxDynamicSharedMemorySize, gemm_smem);
    cudaFuncSetAttribute(gemm_hmma_kernel<1>, cudaFuncAttributeMaxDynamicSharedMemorySize, gemm_smem);
    cudaFuncSetAttribute(attn_hmma_kernel, cudaFuncAttributeMaxDynamicSharedMemorySize, attn_smem);

    // 0) splits
    tsplit_kernel<0><<<dim3(3 * HIDDEN / 32, HIDDEN / 32), dim3(32, 8)>>>(qkv_w, HIDDEN, 3 * HIDDEN);
    tsplit_kernel<1><<<dim3(HIDDEN / 32, HIDDEN / 32), dim3(32, 8)>>>(out_w, HIDDEN, HIDDEN);
    split_kernel<<<(MROWS * HIDDEN) / (256 * 4), 256>>>(x);

    // 1) QKV projection -> bf16 hi/lo qkv
    gemm_hmma_kernel<0><<<dim3(3 * HIDDEN / 128, MROWS / 128), 128, gemm_smem>>>(
        qkv_b, nullptr, 3 * HIDDEN);

    // 2) Flash attention -> bf16 hi/lo ctx
    attn_hmma_kernel<<<dim3(BATCH * HEADS, SEQ / 128), 256, attn_smem>>>();

    // 3) Output projection -> fp32 out
    gemm_hmma_kernel<1><<<dim3(HIDDEN / 128, MROWS / 128), 128, gemm_smem>>>(
        out_b, out, HIDDEN);
}